// round 1
// baseline (speedup 1.0000x reference)
#include <cuda_runtime.h>

// GCN fused kernel for GB300 (sm_103a).
// N nodes, D=32 in-degree, H=128 hidden, K=10 label dim.
//
// out[n,h] = relu( c[h] + x0*W0[0,h] + x1*W0[1,h] + sum_k label[n,k]*W1[k,h]
//                  + P_n*vP[h] + M_n*vM[h] + sum_j n1h[n,j]*W2[j,h] )
// where n1h[n,j] = sum_d feature[src[n,d],j]*et0[n,d]
//       a_nd = w[n,d]*et0[n,d], P_n = sum max(a,0), M_n = sum max(-a,0)
//       vP[h] = sum_j max(Wt4[j],0)*Wt3[j,h], vM[h] = sum_j max(-Wt4[j],0)*Wt3[j,h]
//       c[h] = b0[h]+b1[h]+b2[h]
// (exact identity: relu(a*W) = max(a,0)*max(W,0) + max(-a,0)*max(-W,0))

#define Hd 128
#define Dd 32
#define Kd 10
#define NODES 32
#define NTHREADS 256
#define DPAD 33   // pad D-rows to 33 to kill smem bank conflicts in P/M reduce

__device__ float g_c[Hd];
__device__ float g_vP[Hd];
__device__ float g_vM[Hd];

__global__ void gcn_prep_kernel(const float* __restrict__ b0,
                                const float* __restrict__ b1,
                                const float* __restrict__ b2,
                                const float* __restrict__ Wt3,
                                const float* __restrict__ Wt4) {
    int h = threadIdx.x;  // 0..127
    float vp = 0.f, vm = 0.f;
#pragma unroll 8
    for (int j = 0; j < Hd; ++j) {
        float w4 = Wt4[j];
        float t3 = Wt3[j * Hd + h];
        vp = fmaf(fmaxf(w4, 0.f), t3, vp);
        vm = fmaf(fmaxf(-w4, 0.f), t3, vm);
    }
    g_c[h]  = b0[h] + b1[h] + b2[h];
    g_vP[h] = vp;
    g_vM[h] = vm;
}

// dynamic smem layout (floats):
//  sW2   : 128*128      = 16384
//  sN1   : 32*128       =  4096
//  sSrc  : 32*33 (int)  =  1056
//  sEt   : 32*33        =  1056
//  sWv   : 32*33        =  1056
//  sX    : 32*2         =    64
//  sLab  : 32*10        =   320
//  sP,sM : 32+32        =    64
//  sC,sVP,sVM : 3*128   =   384
//  sW0   : 2*128        =   256
//  sW1   : 10*128       =  1280
// total = 26016 floats  = 104064 bytes
#define SMEM_FLOATS 26016
#define SMEM_BYTES  (SMEM_FLOATS * 4)

__global__ void __launch_bounds__(NTHREADS, 2)
gcn_main_kernel(const float* __restrict__ feature,
                const float* __restrict__ x,
                const float* __restrict__ label,
                const float* __restrict__ w,
                const float* __restrict__ e_type,
                const int*   __restrict__ src,
                const float* __restrict__ W0,
                const float* __restrict__ W1,
                const float* __restrict__ W2,
                float* __restrict__ out,
                int N) {
    extern __shared__ float sm[];
    float* sW2  = sm;                     // 16384
    float* sN1  = sW2 + Hd * Hd;          // 4096
    int*   sSrc = (int*)(sN1 + NODES*Hd); // 1056
    float* sEt  = (float*)(sSrc + NODES*DPAD); // 1056
    float* sWv  = sEt + NODES*DPAD;       // 1056
    float* sX   = sWv + NODES*DPAD;       // 64
    float* sLab = sX + NODES*2;           // 320
    float* sP   = sLab + NODES*Kd;        // 32
    float* sM   = sP + NODES;             // 32
    float* sC   = sM + NODES;             // 128
    float* sVP  = sC + Hd;                // 128
    float* sVM  = sVP + Hd;               // 128
    float* sW0  = sVM + Hd;               // 256
    float* sW1  = sW0 + 2*Hd;             // 1280

    const int t  = threadIdx.x;
    const int nb = blockIdx.x * NODES;

    // ---- stage W2 (64KB) as float4 ----
    {
        const float4* W2v = (const float4*)W2;
        float4* sW2v = (float4*)sW2;
#pragma unroll 4
        for (int i = t; i < Hd * Hd / 4; i += NTHREADS) sW2v[i] = W2v[i];
    }
    // ---- stage small params ----
    if (t < Hd) { sC[t] = g_c[t]; sVP[t] = g_vP[t]; sVM[t] = g_vM[t]; }
    for (int i = t; i < 2 * Hd; i += NTHREADS) sW0[i] = W0[i];
    for (int i = t; i < Kd * Hd; i += NTHREADS) sW1[i] = W1[i];

    // ---- stage per-node edge data (clamped at tail) ----
    for (int i = t; i < NODES * Dd; i += NTHREADS) {
        int nl = i / Dd, d = i % Dd;
        int n = nb + nl;
        bool ok = (n < N);
        int nc = ok ? n : 0;
        sSrc[nl * DPAD + d] = src[nc * Dd + d];
        float e = ok ? e_type[((size_t)nc * Dd + d) * 2] : 0.f;
        sEt[nl * DPAD + d]  = e;
        sWv[nl * DPAD + d]  = ok ? w[nc * Dd + d] : 0.f;
    }
    for (int i = t; i < NODES * 2; i += NTHREADS) {
        int nl = i >> 1; int n = nb + nl;
        sX[i] = (n < N) ? x[(size_t)n * 2 + (i & 1)] : 0.f;
    }
    for (int i = t; i < NODES * Kd; i += NTHREADS) {
        int nl = i / Kd; int n = nb + nl;
        sLab[i] = (n < N) ? label[(size_t)n * Kd + (i - nl * Kd)] : 0.f;
    }
    __syncthreads();

    // ---- per-node scalar reduction P/M (warp 0; DPAD makes this conflict-free) ----
    if (t < NODES) {
        float P = 0.f, M = 0.f;
#pragma unroll
        for (int d = 0; d < Dd; ++d) {
            float a = sWv[t * DPAD + d] * sEt[t * DPAD + d];
            P += fmaxf(a, 0.f);
            M += fmaxf(-a, 0.f);
        }
        sP[t] = P; sM[t] = M;
    }

    // ---- gather phase: n1h[nl, j] = sum_d feature[src, j] * et0 ----
    {
        const int u = t >> 7;      // half: 0/1
        const int j = t & 127;     // h-index
#pragma unroll 1
        for (int i = 0; i < NODES / 2; ++i) {
            int nl = u * (NODES / 2) + i;
            float acc = 0.f;
#pragma unroll 16
            for (int d = 0; d < Dd; ++d) {
                int s   = sSrc[nl * DPAD + d];      // broadcast
                float e = sEt[nl * DPAD + d];       // broadcast
                acc = fmaf(feature[(size_t)s * Hd + j], e, acc);
            }
            sN1[nl * Hd + j] = acc;
        }
    }
    __syncthreads();

    // ---- GEMM phase: 4 nodes x 4 h per thread ----
    const int hq = (t & 31) * 4;   // h base (float4-aligned)
    const int g  = t >> 5;         // node group 0..7 (4 nodes each)
    float acc[4][4];

    // base init: c + x@W0 + P*vP + M*vM
    {
        float4 cv  = *(const float4*)&sC[hq];
        float4 w00 = *(const float4*)&sW0[hq];
        float4 w01 = *(const float4*)&sW0[Hd + hq];
        float4 vp  = *(const float4*)&sVP[hq];
        float4 vm  = *(const float4*)&sVM[hq];
#pragma unroll
        for (int n = 0; n < 4; ++n) {
            int nl = g * 4 + n;
            float x0 = sX[nl * 2], x1 = sX[nl * 2 + 1];
            float Pv = sP[nl], Mv = sM[nl];
            acc[n][0] = cv.x + x0*w00.x + x1*w01.x + Pv*vp.x + Mv*vm.x;
            acc[n][1] = cv.y + x0*w00.y + x1*w01.y + Pv*vp.y + Mv*vm.y;
            acc[n][2] = cv.z + x0*w00.z + x1*w01.z + Pv*vp.z + Mv*vm.z;
            acc[n][3] = cv.w + x0*w00.w + x1*w01.w + Pv*vp.w + Mv*vm.w;
        }
        // + label @ W1
#pragma unroll
        for (int k = 0; k < Kd; ++k) {
            float4 w1v = *(const float4*)&sW1[k * Hd + hq];
#pragma unroll
            for (int n = 0; n < 4; ++n) {
                float lab = sLab[(g * 4 + n) * Kd + k];
                acc[n][0] = fmaf(lab, w1v.x, acc[n][0]);
                acc[n][1] = fmaf(lab, w1v.y, acc[n][1]);
                acc[n][2] = fmaf(lab, w1v.z, acc[n][2]);
                acc[n][3] = fmaf(lab, w1v.w, acc[n][3]);
            }
        }
    }

    // + n1h @ W2
#pragma unroll 4
    for (int j = 0; j < Hd; ++j) {
        float4 wv = *(const float4*)&sW2[j * Hd + hq];
#pragma unroll
        for (int n = 0; n < 4; ++n) {
            float a = sN1[(g * 4 + n) * Hd + j];   // broadcast within warp
            acc[n][0] = fmaf(a, wv.x, acc[n][0]);
            acc[n][1] = fmaf(a, wv.y, acc[n][1]);
            acc[n][2] = fmaf(a, wv.z, acc[n][2]);
            acc[n][3] = fmaf(a, wv.w, acc[n][3]);
        }
    }

    // relu + store (coalesced float4)
#pragma unroll
    for (int n = 0; n < 4; ++n) {
        int gn = nb + g * 4 + n;
        if (gn < N) {
            float4 o;
            o.x = fmaxf(acc[n][0], 0.f);
            o.y = fmaxf(acc[n][1], 0.f);
            o.z = fmaxf(acc[n][2], 0.f);
            o.w = fmaxf(acc[n][3], 0.f);
            *(float4*)&out[(size_t)gn * Hd + hq] = o;
        }
    }
}

extern "C" void kernel_launch(void* const* d_in, const int* in_sizes, int n_in,
                              void* d_out, int out_size) {
    const float* feature = (const float*)d_in[0];
    const float* x       = (const float*)d_in[1];
    const float* label   = (const float*)d_in[2];
    const float* w       = (const float*)d_in[3];
    const float* e_type  = (const float*)d_in[4];
    const int*   src     = (const int*)  d_in[5];
    const float* W0      = (const float*)d_in[6];
    const float* b0      = (const float*)d_in[7];
    const float* W1      = (const float*)d_in[8];
    const float* b1      = (const float*)d_in[9];
    const float* W2      = (const float*)d_in[10];
    const float* b2      = (const float*)d_in[11];
    const float* Wt3     = (const float*)d_in[12];
    const float* Wt4     = (const float*)d_in[13];
    float* out = (float*)d_out;

    int N = in_sizes[1] / 2;  // x is [N,2]

    cudaFuncSetAttribute(gcn_main_kernel,
                         cudaFuncAttributeMaxDynamicSharedMemorySize, SMEM_BYTES);

    gcn_prep_kernel<<<1, Hd>>>(b0, b1, b2, Wt3, Wt4);

    int grid = (N + NODES - 1) / NODES;
    gcn_main_kernel<<<grid, NTHREADS, SMEM_BYTES>>>(
        feature, x, label, w, e_type, src, W0, W1, W2, out, N);
}

// round 6
// speedup vs baseline: 1.1646x; 1.1646x over previous
#include <cuda_runtime.h>

// GCN fused kernel for GB300 (sm_103a), round 2 design (5th submit — four
// prior benches died on broker GPUAcquisitionTimeout; kernel never executed).
// Identity used (exact): relu(a*W) = max(a,0)*max(W,0) + max(-a,0)*max(-W,0)
//  -> s@Wt3 = P_n*vP + M_n*vM with vP/vM precomputed from Wt4/Wt3.
//
// out[n,h] = relu( c[h] + x0*W0[0,h] + x1*W0[1,h] + sum_k label[n,k]*W1[k,h]
//                  + P_n*vP[h] + M_n*vM[h] + sum_j n1h[n,j]*W2[j,h] )
// n1h[n,j] = sum_d feature[src[n,d],j]*et0[n,d]
//
// Key choices: packed f32x2 FMA (SASS FFMA2), 64 nodes/block, 4 CTAs/SM
// (52.7KB smem, <=64 regs), single wave (469 blocks), W2 via __ldg (L2-shared).

#define Hd 128
#define Dd 32
#define Kd 10
#define NODES 64
#define NT 256

typedef unsigned long long u64;

__device__ __align__(16) float g_c[Hd];
__device__ __align__(16) float g_vP[Hd];
__device__ __align__(16) float g_vM[Hd];

__device__ __forceinline__ u64 pack2(float a, float b) {
    u64 r; asm("mov.b64 %0, {%1, %2};" : "=l"(r) : "f"(a), "f"(b)); return r;
}
__device__ __forceinline__ void unpack2(u64 v, float& a, float& b) {
    asm("mov.b64 {%0, %1}, %2;" : "=f"(a), "=f"(b) : "l"(v));
}
__device__ __forceinline__ u64 fma2(u64 a, u64 b, u64 c) {
    u64 r; asm("fma.rn.f32x2 %0, %1, %2, %3;" : "=l"(r) : "l"(a), "l"(b), "l"(c)); return r;
}
__device__ __forceinline__ u64 add2(u64 a, u64 b) {
    u64 r; asm("add.rn.f32x2 %0, %1, %2;" : "=l"(r) : "l"(a), "l"(b)); return r;
}

// ---------------- prep: c = b0+b1+b2 ; vP/vM from Wt4/Wt3 ----------------
__global__ void gcn_prep_kernel(const float* __restrict__ b0,
                                const float* __restrict__ b1,
                                const float* __restrict__ b2,
                                const float* __restrict__ Wt3,
                                const float* __restrict__ Wt4) {
    __shared__ float pp[4][Hd], pm[4][Hd];
    int h = threadIdx.x & 127;
    int part = threadIdx.x >> 7;   // 0..3
    float vp = 0.f, vm = 0.f;
#pragma unroll 8
    for (int j = part * 32; j < part * 32 + 32; ++j) {
        float w4 = __ldg(&Wt4[j]);
        float t3 = __ldg(&Wt3[j * Hd + h]);
        vp = fmaf(fmaxf(w4, 0.f), t3, vp);
        vm = fmaf(fmaxf(-w4, 0.f), t3, vm);
    }
    pp[part][h] = vp; pm[part][h] = vm;
    __syncthreads();
    if (threadIdx.x < Hd) {
        g_c[h]  = b0[h] + b1[h] + b2[h];
        g_vP[h] = pp[0][h] + pp[1][h] + pp[2][h] + pp[3][h];
        g_vM[h] = pm[0][h] + pm[1][h] + pm[2][h] + pm[3][h];
    }
}

// smem layout (bytes):
//  sN1  : 64*128*4 = 32768   [node][h]
//  sSrc : 64*32*4  =  8192
//  sEt  : 64*32*4  =  8192
//  sLab : 64*10*4  =  2560
//  sX   : 64*2*4   =   512
//  sP   : 64*4     =   256
//  sM   : 64*4     =   256
// total = 52736
#define SMEM_BYTES 52736

__global__ void __launch_bounds__(NT, 4)
gcn_main_kernel(const float* __restrict__ feature,
                const float* __restrict__ x,
                const float* __restrict__ label,
                const float* __restrict__ w,
                const float* __restrict__ e_type,
                const int*   __restrict__ src,
                const float* __restrict__ W0,
                const float* __restrict__ W1,
                const float* __restrict__ W2,
                float* __restrict__ out,
                int N) {
    extern __shared__ char smraw[];
    float* sN1  = (float*)smraw;                 // 32768
    int*   sSrc = (int*)  (smraw + 32768);       // 8192
    float* sEt  = (float*)(smraw + 40960);       // 8192
    float* sLab = (float*)(smraw + 49152);       // 2560
    float* sX   = (float*)(smraw + 51712);       // 512
    float* sP   = (float*)(smraw + 52224);       // 256
    float* sM   = (float*)(smraw + 52480);       // 256

    const int t  = threadIdx.x;
    const int nb = blockIdx.x * NODES;

    // ---- stage edges + fused P/M warp reduction ----
    // 2048 elements / 256 threads = 8 full-warp iterations; lane == d.
#pragma unroll
    for (int i = t; i < NODES * Dd; i += NT) {
        int nl = i >> 5, d = i & 31;
        int n = nb + nl;
        bool ok = (n < N);
        int nc = ok ? n : 0;
        int   s  = src[nc * Dd + d];
        float e  = ok ? __ldg(&e_type[(size_t)(nc * Dd + d) * 2]) : 0.f;
        float wv = ok ? __ldg(&w[nc * Dd + d]) : 0.f;
        sSrc[i] = s;
        sEt[i]  = e;
        float a = wv * e;
        float P = fmaxf(a, 0.f), M = fmaxf(-a, 0.f);
#pragma unroll
        for (int o = 16; o; o >>= 1) {
            P += __shfl_xor_sync(0xffffffffu, P, o);
            M += __shfl_xor_sync(0xffffffffu, M, o);
        }
        if (d == 0) { sP[nl] = P; sM[nl] = M; }
    }
    // ---- stage x, label ----
    for (int i = t; i < NODES * 2; i += NT) {
        int nl = i >> 1; int n = nb + nl;
        sX[i] = (n < N) ? x[(size_t)n * 2 + (i & 1)] : 0.f;
    }
    for (int i = t; i < NODES * Kd; i += NT) {
        int nl = i / Kd; int n = nb + nl;
        sLab[i] = (n < N) ? label[(size_t)n * Kd + (i - nl * Kd)] : 0.f;
    }
    __syncthreads();

    // ---- gather: n1h[nl][h] = sum_d feature[src][h] * et0, packed f32x2 ----
    {
        const int j2  = t & 63;        // h-pair index 0..63
        const int q   = t >> 6;        // node quarter 0..3
        const int col = 2 * j2;
#pragma unroll 1
        for (int i = 0; i < NODES / 4; ++i) {
            const int nl = q * (NODES / 4) + i;
            const int*   sp = sSrc + nl * Dd;
            const float* ep = sEt  + nl * Dd;
            u64 aa = 0ull, ab = 0ull;     // two chains to break serial dep
#pragma unroll 8
            for (int d = 0; d < Dd; d += 2) {
                int   s0 = sp[d];     float e0 = ep[d];
                int   s1 = sp[d + 1]; float e1 = ep[d + 1];
                u64 f0 = __ldg((const u64*)(feature + s0 * Hd + col));
                u64 f1 = __ldg((const u64*)(feature + s1 * Hd + col));
                aa = fma2(f0, pack2(e0, e0), aa);
                ab = fma2(f1, pack2(e1, e1), ab);
            }
            *(u64*)(sN1 + nl * Hd + col) = add2(aa, ab);
        }
    }
    __syncthreads();

    // ---- GEMM: 8 nodes x 4 h per thread, f32x2 packed accumulators ----
    const int hq = (t & 31) * 4;       // h base, 16B aligned
    const int g  = t >> 5;             // node group 0..7
    const float* sNg = sN1 + g * 8 * Hd;

    u64 a01[8], a23[8];
#pragma unroll
    for (int n = 0; n < 8; ++n) { a01[n] = 0ull; a23[n] = 0ull; }

    const float* W2h = W2 + hq;
#pragma unroll 4
    for (int j = 0; j < Hd; ++j) {
        ulonglong2 wc = __ldg((const ulonglong2*)(W2h + j * Hd));
        const float* np = sNg + j;
#pragma unroll
        for (int n = 0; n < 8; ++n) {
            float a = np[n * Hd];          // broadcast LDS
            u64 aa = pack2(a, a);
            a01[n] = fma2(aa, wc.x, a01[n]);
            a23[n] = fma2(aa, wc.y, a23[n]);
        }
    }

    // ---- epilogue: + label@W1 + c + x@W0 + P*vP + M*vM ----
#pragma unroll
    for (int k = 0; k < Kd; ++k) {
        u64 w101 = __ldg((const u64*)(W1 + k * Hd + hq));
        u64 w123 = __ldg((const u64*)(W1 + k * Hd + hq + 2));
#pragma unroll
        for (int n = 0; n < 8; ++n) {
            float lk = sLab[(g * 8 + n) * Kd + k];
            u64 ll = pack2(lk, lk);
            a01[n] = fma2(ll, w101, a01[n]);
            a23[n] = fma2(ll, w123, a23[n]);
        }
    }
    {
        u64 c01  = __ldg((const u64*)(g_c  + hq)), c23  = __ldg((const u64*)(g_c  + hq + 2));
        u64 p01  = __ldg((const u64*)(g_vP + hq)), p23  = __ldg((const u64*)(g_vP + hq + 2));
        u64 m01  = __ldg((const u64*)(g_vM + hq)), m23  = __ldg((const u64*)(g_vM + hq + 2));
        u64 wa01 = __ldg((const u64*)(W0 + hq)),      wa23 = __ldg((const u64*)(W0 + hq + 2));
        u64 wb01 = __ldg((const u64*)(W0 + Hd + hq)), wb23 = __ldg((const u64*)(W0 + Hd + hq + 2));
#pragma unroll
        for (int n = 0; n < 8; ++n) {
            int nl = g * 8 + n;
            u64 x0 = pack2(sX[2 * nl], sX[2 * nl]);
            u64 x1 = pack2(sX[2 * nl + 1], sX[2 * nl + 1]);
            u64 Pv = pack2(sP[nl], sP[nl]);
            u64 Mv = pack2(sM[nl], sM[nl]);
            a01[n] = fma2(x0, wa01, a01[n]);
            a23[n] = fma2(x0, wa23, a23[n]);
            a01[n] = fma2(x1, wb01, a01[n]);
            a23[n] = fma2(x1, wb23, a23[n]);
            a01[n] = fma2(Pv, p01, a01[n]);
            a23[n] = fma2(Pv, p23, a23[n]);
            a01[n] = fma2(Mv, m01, a01[n]);
            a23[n] = fma2(Mv, m23, a23[n]);
            a01[n] = add2(a01[n], c01);
            a23[n] = add2(a23[n], c23);
        }
    }

    // ---- relu + coalesced float4 store ----
#pragma unroll
    for (int n = 0; n < 8; ++n) {
        int gn = nb + g * 8 + n;
        if (gn < N) {
            float o0, o1, o2, o3;
            unpack2(a01[n], o0, o1);
            unpack2(a23[n], o2, o3);
            float4 o;
            o.x = fmaxf(o0, 0.f); o.y = fmaxf(o1, 0.f);
            o.z = fmaxf(o2, 0.f); o.w = fmaxf(o3, 0.f);
            *(float4*)(out + (size_t)gn * Hd + hq) = o;
        }
    }
}

extern "C" void kernel_launch(void* const* d_in, const int* in_sizes, int n_in,
                              void* d_out, int out_size) {
    const float* feature = (const float*)d_in[0];
    const float* x       = (const float*)d_in[1];
    const float* label   = (const float*)d_in[2];
    const float* w       = (const float*)d_in[3];
    const float* e_type  = (const float*)d_in[4];
    const int*   src     = (const int*)  d_in[5];
    const float* W0      = (const float*)d_in[6];
    const float* b0      = (const float*)d_in[7];
    const float* W1      = (const float*)d_in[8];
    const float* b1      = (const float*)d_in[9];
    const float* W2      = (const float*)d_in[10];
    const float* b2      = (const float*)d_in[11];
    const float* Wt3     = (const float*)d_in[12];
    const float* Wt4     = (const float*)d_in[13];
    float* out = (float*)d_out;

    int N = in_sizes[1] / 2;  // x is [N,2]

    cudaFuncSetAttribute(gcn_main_kernel,
                         cudaFuncAttributeMaxDynamicSharedMemorySize, SMEM_BYTES);

    gcn_prep_kernel<<<1, 512>>>(b0, b1, b2, Wt3, Wt4);

    int grid = (N + NODES - 1) / NODES;
    gcn_main_kernel<<<grid, NT, SMEM_BYTES>>>(
        feature, x, label, w, e_type, src, W0, W1, W2, out, N);
}

// round 17
// speedup vs baseline: 1.5805x; 1.3571x over previous
#include <cuda_runtime.h>

// GCN fused kernel for GB300 (sm_103a), round 7 design (11th submit — ten
// prior benches died on broker GPUAcquisitionTimeout; kernel never executed).
// Identity (exact): relu(a*W) = max(a,0)*max(W,0) + max(-a,0)*max(-W,0)
//  -> s@Wt3 = P_n*vP + M_n*vM with vP/vM precomputed from Wt4/Wt3.
//
// R7 changes vs R6 (86.3us):
//  - 512 thr/CTA, 2 CTAs/SM, NODES=112 -> grid 268 of 296 slots (90.5% fill,
//    single wave) vs 469/592 (79%): occupancy 37.7% -> ~45%.
//  - gather: 1 warp per node, LDG.128 (lane=4 h), src stored as premultiplied
//    byte offsets, et0 stored pre-duplicated u64 -> no pack MOV, no IMAD.WIDE.
//  - GEMM unchanged in structure: 7 nodes x 4 h per thread, f32x2 FFMA2.

#define Hd 128
#define Dd 32
#define Kd 10
#define NODES 112
#define NT 512
#define NPG 7            // nodes per GEMM group (16 groups * 7 = 112)

typedef unsigned long long u64;

__device__ __align__(16) float g_c[Hd];
__device__ __align__(16) float g_vP[Hd];
__device__ __align__(16) float g_vM[Hd];

__device__ __forceinline__ u64 pack2(float a, float b) {
    u64 r; asm("mov.b64 %0, {%1, %2};" : "=l"(r) : "f"(a), "f"(b)); return r;
}
__device__ __forceinline__ void unpack2(u64 v, float& a, float& b) {
    asm("mov.b64 {%0, %1}, %2;" : "=f"(a), "=f"(b) : "l"(v));
}
__device__ __forceinline__ u64 fma2(u64 a, u64 b, u64 c) {
    u64 r; asm("fma.rn.f32x2 %0, %1, %2, %3;" : "=l"(r) : "l"(a), "l"(b), "l"(c)); return r;
}
__device__ __forceinline__ u64 add2(u64 a, u64 b) {
    u64 r; asm("add.rn.f32x2 %0, %1, %2;" : "=l"(r) : "l"(a), "l"(b)); return r;
}

// ---------------- prep: c = b0+b1+b2 ; vP/vM from Wt4/Wt3 ----------------
__global__ void gcn_prep_kernel(const float* __restrict__ b0,
                                const float* __restrict__ b1,
                                const float* __restrict__ b2,
                                const float* __restrict__ Wt3,
                                const float* __restrict__ Wt4) {
    __shared__ float pp[4][Hd], pm[4][Hd];
    int h = threadIdx.x & 127;
    int part = threadIdx.x >> 7;   // 0..3
    float vp = 0.f, vm = 0.f;
#pragma unroll 8
    for (int j = part * 32; j < part * 32 + 32; ++j) {
        float w4 = __ldg(&Wt4[j]);
        float t3 = __ldg(&Wt3[j * Hd + h]);
        vp = fmaf(fmaxf(w4, 0.f), t3, vp);
        vm = fmaf(fmaxf(-w4, 0.f), t3, vm);
    }
    pp[part][h] = vp; pm[part][h] = vm;
    __syncthreads();
    if (threadIdx.x < Hd) {
        g_c[h]  = b0[h] + b1[h] + b2[h];
        g_vP[h] = pp[0][h] + pp[1][h] + pp[2][h] + pp[3][h];
        g_vM[h] = pm[0][h] + pm[1][h] + pm[2][h] + pm[3][h];
    }
}

// smem layout (bytes), NODES=112:
//  sN1    : 112*128*4 = 57344
//  sEtDup : 112*32*8  = 28672   (et0 duplicated into both f32x2 halves)
//  sSrcOff: 112*32*4  = 14336   (src * 512 byte offsets)
//  sLab   : 112*10*4  =  4480
//  sX     : 112*2*4   =   896
//  sP     : 112*4     =   448
//  sM     : 112*4     =   448
// total = 106624  (x2 CTAs = 213248 <= 228KB)
#define SMEM_BYTES 106624

__global__ void __launch_bounds__(NT, 2)
gcn_main_kernel(const float* __restrict__ feature,
                const float* __restrict__ x,
                const float* __restrict__ label,
                const float* __restrict__ w,
                const float* __restrict__ e_type,
                const int*   __restrict__ src,
                const float* __restrict__ W0,
                const float* __restrict__ W1,
                const float* __restrict__ W2,
                float* __restrict__ out,
                int N) {
    extern __shared__ char smraw[];
    float* sN1    = (float*)smraw;                    // 57344
    u64*   sEtDup = (u64*)  (smraw + 57344);          // 28672
    int*   sSrcOff= (int*)  (smraw + 86016);          // 14336
    float* sLab   = (float*)(smraw + 100352);         // 4480
    float* sX     = (float*)(smraw + 104832);         // 896
    float* sP     = (float*)(smraw + 105728);         // 448
    float* sM     = (float*)(smraw + 106176);         // 448

    const int t    = threadIdx.x;
    const int lane = t & 31;
    const int wid  = t >> 5;               // 0..15
    const int nb   = blockIdx.x * NODES;

    // ---- stage edges + fused P/M warp reduction (lane == d invariant) ----
    // NODES*Dd = 3584 = 7 * 512 exact.
#pragma unroll
    for (int i = t; i < NODES * Dd; i += NT) {
        int nl = i >> 5, d = i & 31;
        int n = nb + nl;
        bool ok = (n < N);
        int nc = ok ? n : 0;
        int   s  = src[nc * Dd + d];
        float e  = ok ? __ldg(&e_type[(size_t)(nc * Dd + d) * 2]) : 0.f;
        float wv = ok ? __ldg(&w[nc * Dd + d]) : 0.f;
        sSrcOff[i] = s * (Hd * 4);         // byte offset into feature
        sEtDup[i]  = pack2(e, e);
        float a = wv * e;
        float P = fmaxf(a, 0.f), M = fmaxf(-a, 0.f);
#pragma unroll
        for (int o = 16; o; o >>= 1) {
            P += __shfl_xor_sync(0xffffffffu, P, o);
            M += __shfl_xor_sync(0xffffffffu, M, o);
        }
        if (d == 0) { sP[nl] = P; sM[nl] = M; }
    }
    // ---- stage x, label ----
    for (int i = t; i < NODES * 2; i += NT) {
        int nl = i >> 1; int n = nb + nl;
        sX[i] = (n < N) ? x[(size_t)n * 2 + (i & 1)] : 0.f;
    }
    for (int i = t; i < NODES * Kd; i += NT) {
        int nl = i / Kd; int n = nb + nl;
        sLab[i] = (n < N) ? label[(size_t)n * Kd + (i - nl * Kd)] : 0.f;
    }
    __syncthreads();

    // ---- gather: warp per node, lane = 4 h via LDG.128 ----
    // n1h[nl][4l..4l+3] = sum_d feature[srcoff][..] * etdup
    {
        const char* fbase = (const char*)feature + lane * 16;  // lane's 16B slot
#pragma unroll 1
        for (int i = 0; i < NPG; ++i) {
            const int nl = wid * NPG + i;
            const int* so = sSrcOff + nl * Dd;
            const u64* se = sEtDup  + nl * Dd;
            u64 aA0 = 0ull, aA1 = 0ull;      // even-d chain
            u64 aB0 = 0ull, aB1 = 0ull;      // odd-d chain
#pragma unroll 4
            for (int d = 0; d < Dd; d += 2) {
                int o0 = so[d];     u64 e0 = se[d];       // broadcast LDS
                int o1 = so[d + 1]; u64 e1 = se[d + 1];
                ulonglong2 f0 = __ldg((const ulonglong2*)(fbase + o0));
                ulonglong2 f1 = __ldg((const ulonglong2*)(fbase + o1));
                aA0 = fma2(f0.x, e0, aA0);
                aA1 = fma2(f0.y, e0, aA1);
                aB0 = fma2(f1.x, e1, aB0);
                aB1 = fma2(f1.y, e1, aB1);
            }
            ulonglong2 r;
            r.x = add2(aA0, aB0);
            r.y = add2(aA1, aB1);
            *(ulonglong2*)(sN1 + nl * Hd + lane * 4) = r;   // STS.128
        }
    }
    __syncthreads();

    // ---- GEMM: 7 nodes x 4 h per thread, f32x2 packed accumulators ----
    const int hq = lane * 4;               // h base, 16B aligned
    const int g  = wid;                    // node group 0..15
    const float* sNg = sN1 + g * NPG * Hd;

    u64 a01[NPG], a23[NPG];
#pragma unroll
    for (int n = 0; n < NPG; ++n) { a01[n] = 0ull; a23[n] = 0ull; }

    const float* W2h = W2 + hq;
#pragma unroll 4
    for (int j = 0; j < Hd; ++j) {
        ulonglong2 wc = __ldg((const ulonglong2*)(W2h + j * Hd));
        const float* np = sNg + j;
#pragma unroll
        for (int n = 0; n < NPG; ++n) {
            float a = np[n * Hd];          // broadcast LDS
            u64 aa = pack2(a, a);
            a01[n] = fma2(aa, wc.x, a01[n]);
            a23[n] = fma2(aa, wc.y, a23[n]);
        }
    }

    // ---- epilogue: + label@W1 ----
#pragma unroll
    for (int k = 0; k < Kd; ++k) {
        u64 w101 = __ldg((const u64*)(W1 + k * Hd + hq));
        u64 w123 = __ldg((const u64*)(W1 + k * Hd + hq + 2));
#pragma unroll
        for (int n = 0; n < NPG; ++n) {
            float lk = sLab[(g * NPG + n) * Kd + k];
            u64 ll = pack2(lk, lk);
            a01[n] = fma2(ll, w101, a01[n]);
            a23[n] = fma2(ll, w123, a23[n]);
        }
    }
    // ---- + x@W0 ----
    {
        u64 wa01 = __ldg((const u64*)(W0 + hq)),      wa23 = __ldg((const u64*)(W0 + hq + 2));
        u64 wb01 = __ldg((const u64*)(W0 + Hd + hq)), wb23 = __ldg((const u64*)(W0 + Hd + hq + 2));
#pragma unroll
        for (int n = 0; n < NPG; ++n) {
            int nl = g * NPG + n;
            u64 x0 = pack2(sX[2 * nl], sX[2 * nl]);
            u64 x1 = pack2(sX[2 * nl + 1], sX[2 * nl + 1]);
            a01[n] = fma2(x0, wa01, a01[n]);
            a23[n] = fma2(x0, wa23, a23[n]);
            a01[n] = fma2(x1, wb01, a01[n]);
            a23[n] = fma2(x1, wb23, a23[n]);
        }
    }
    // ---- + P*vP + M*vM + c ----
    {
        u64 p01 = __ldg((const u64*)(g_vP + hq)), p23 = __ldg((const u64*)(g_vP + hq + 2));
        u64 m01 = __ldg((const u64*)(g_vM + hq)), m23 = __ldg((const u64*)(g_vM + hq + 2));
        u64 c01 = __ldg((const u64*)(g_c  + hq)), c23 = __ldg((const u64*)(g_c  + hq + 2));
#pragma unroll
        for (int n = 0; n < NPG; ++n) {
            int nl = g * NPG + n;
            u64 Pv = pack2(sP[nl], sP[nl]);
            u64 Mv = pack2(sM[nl], sM[nl]);
            a01[n] = fma2(Pv, p01, a01[n]);
            a23[n] = fma2(Pv, p23, a23[n]);
            a01[n] = fma2(Mv, m01, a01[n]);
            a23[n] = fma2(Mv, m23, a23[n]);
            a01[n] = add2(a01[n], c01);
            a23[n] = add2(a23[n], c23);
        }
    }

    // ---- relu + coalesced float4 store ----
#pragma unroll
    for (int n = 0; n < NPG; ++n) {
        int gn = nb + g * NPG + n;
        if (gn < N) {
            float o0, o1, o2, o3;
            unpack2(a01[n], o0, o1);
            unpack2(a23[n], o2, o3);
            float4 o;
            o.x = fmaxf(o0, 0.f); o.y = fmaxf(o1, 0.f);
            o.z = fmaxf(o2, 0.f); o.w = fmaxf(o3, 0.f);
            *(float4*)(out + (size_t)gn * Hd + hq) = o;
        }
    }
}

extern "C" void kernel_launch(void* const* d_in, const int* in_sizes, int n_in,
                              void* d_out, int out_size) {
    const float* feature = (const float*)d_in[0];
    const float* x       = (const float*)d_in[1];
    const float* label   = (const float*)d_in[2];
    const float* w       = (const float*)d_in[3];
    const float* e_type  = (const float*)d_in[4];
    const int*   src     = (const int*)  d_in[5];
    const float* W0      = (const float*)d_in[6];
    const float* b0      = (const float*)d_in[7];
    const float* W1      = (const float*)d_in[8];
    const float* b1      = (const float*)d_in[9];
    const float* W2      = (const float*)d_in[10];
    const float* b2      = (const float*)d_in[11];
    const float* Wt3     = (const float*)d_in[12];
    const float* Wt4     = (const float*)d_in[13];
    float* out = (float*)d_out;

    int N = in_sizes[1] / 2;  // x is [N,2]

    cudaFuncSetAttribute(gcn_main_kernel,
                         cudaFuncAttributeMaxDynamicSharedMemorySize, SMEM_BYTES);

    gcn_prep_kernel<<<1, 512>>>(b0, b1, b2, Wt3, Wt4);

    int grid = (N + NODES - 1) / NODES;   // 268
    gcn_main_kernel<<<grid, NT, SMEM_BYTES>>>(
        feature, x, label, w, e_type, src, W0, W1, W2, out, N);
}